// round 10
// baseline (speedup 1.0000x reference)
#include <cuda_runtime.h>
#include <cstdint>

// ---------------- problem constants ----------------
#define NN      100000
#define EE      250000
#define HH      4
#define HD      128
#define NOUT    349
#define MTILES  782                    // ceil(NN/128)
#define TW      16384                  // frag words per (tile)  (4 chunks x 4096)

// ---------------- device scratch ----------------
__device__ float    g_H  [3ll * NN * HD];       // per-relation h = x@W (row-major)
__device__ uint32_t g_XSF[2ll * MTILES * TW];   // frag images of x_paper, x_author
__device__ uint32_t g_XF [3ll * MTILES * TW];   // frag images of XP1, XA1, XP2
__device__ float    g_P  [7ll * NN * HH];       // attention logit buffers [n*4+h]
__device__ float    g_V  [3 * HD * HH];         // W·att_d vectors
__device__ float    g_LB2[NOUT];                // folded classifier bias
__device__ uint32_t g_WF [8 * TW];              // pre-fragmented tf32 B matrices
__device__ int      g_CNT[3 * NN];
__device__ int      g_CUR[3 * NN];
__device__ int      g_OFF[3 * (NN + 1)];
__device__ int      g_SRC[3ll * EE];

__device__ __forceinline__ uint32_t f2tf32(float x) {
    uint32_t r; asm("cvt.rna.tf32.f32 %0, %1;" : "=r"(r) : "f"(x)); return r;
}

// ---------------- CSR build ----------------
struct EdgeP { const int* ei[3]; int* cnt; int* cur; int* srcout; };

__global__ void hist_kernel(EdgeP p)
{
    int rel = blockIdx.y;
    int e = blockIdx.x * blockDim.x + threadIdx.x;
    if (e >= EE) return;
    int dst = p.ei[rel][EE + e];
    atomicAdd(&p.cnt[rel * NN + dst], 1);
}

__global__ void __launch_bounds__(1024) scan_kernel(const int* cnt, int* off, int* cur)
{
    int rel = blockIdx.x;
    const int* c = cnt + (size_t)rel * NN;
    int* o  = off + (size_t)rel * (NN + 1);
    int* cu = cur + (size_t)rel * NN;

    __shared__ int wsum[32];
    __shared__ int sbase;
    int tid = threadIdx.x, lane = tid & 31, wid = tid >> 5;
    if (tid == 0) sbase = 0;
    __syncthreads();

    for (int start = 0; start < NN; start += 1024) {
        int i = start + tid;
        int orig = (i < NN) ? c[i] : 0;
        int v = orig;
        #pragma unroll
        for (int d = 1; d < 32; d <<= 1) {
            int t = __shfl_up_sync(0xffffffff, v, d);
            if (lane >= d) v += t;
        }
        if (lane == 31) wsum[wid] = v;
        __syncthreads();
        if (wid == 0) {
            int s = wsum[lane];
            #pragma unroll
            for (int d = 1; d < 32; d <<= 1) {
                int t = __shfl_up_sync(0xffffffff, s, d);
                if (lane >= d) s += t;
            }
            wsum[lane] = s;
        }
        __syncthreads();
        int wpre = (wid == 0) ? 0 : wsum[wid - 1];
        int excl = sbase + wpre + (v - orig);
        if (i < NN) { o[i] = excl; cu[i] = excl; }
        __syncthreads();
        if (tid == 0) sbase += wsum[31];
        __syncthreads();
    }
    if (tid == 0) o[NN] = EE;
}

__global__ void fill_kernel(EdgeP p)
{
    int rel = blockIdx.y;
    int e = blockIdx.x * blockDim.x + threadIdx.x;
    if (e >= EE) return;
    int src = p.ei[rel][e];
    int dst = p.ei[rel][EE + e];
    int pos = atomicAdd(&p.cur[rel * NN + dst], 1);
    p.srcout[(size_t)rel * EE + pos] = src;
}

// ---------------- prep: V + B frags + folded bias + xs frag images ---------
// blocks 0..2     : V = W·att_d vectors
// blocks 3..514   : fragment-convert 5 relation W's + 3 padded linW tiles
// blocks 515..558 : folded classifier bias (warp per output)
// blocks 559..    : fragment-convert x_paper / x_author (warp per (c,k8,m16))
struct PrepParams {
    const float* Wv[3];
    const float* att[3];
    float* V;
    const float* Wm[5];
    const float* linW;
    uint32_t* WF;
    const float* linb;
    const float* bc;
    const float* bw;
    float* linb2;
    const float* xs[2];
    uint32_t* XSF[2];
};

#define XS_TASKS (2 * MTILES * 128)
#define XS_BLOCKS (XS_TASKS / 8)

__global__ void prep_all_kernel(PrepParams p)
{
    int b = blockIdx.x;
    if (b < 3) {
        int k = threadIdx.x;
        if (k >= HD) return;
        const float* W   = p.Wv[b];
        const float* att = p.att[b];
        #pragma unroll
        for (int h = 0; h < HH; h++) {
            float s = 0.f;
            #pragma unroll
            for (int c = 0; c < 32; c++)
                s += W[k * HD + h * 32 + c] * att[h * 32 + c];
            p.V[b * (HD * HH) + k * HH + h] = s;
        }
    } else if (b < 515) {
        int t = (b - 3) * 256 + threadIdx.x;   // 0..131071
        int m   = t >> 14;                     // matrix 0..7
        int idx = t & 16383;
        int n   = idx & 127;
        int kr  = idx >> 7;
        float val;
        if (m < 5) {
            val = p.Wm[m][kr * HD + n];
        } else {
            int col = (m - 5) * 128 + n;
            val = (col < NOUT) ? p.linW[(size_t)kr * NOUT + col] : 0.f;
        }
        int c = kr >> 5, krl = kr & 31;
        uint32_t word = (uint32_t)(((krl >> 3) * 16 + (n >> 3)) * 64
                                   + ((n & 7) * 4 + (krl & 3)) * 2
                                   + ((krl >> 2) & 1));
        p.WF[m * TW + c * 4096 + word] = f2tf32(val);
    } else if (b < 559) {
        int wo   = (b - 515) * 8 + (threadIdx.x >> 5);
        int lane = threadIdx.x & 31;
        if (wo >= NOUT) return;
        float s = 0.f;
        #pragma unroll
        for (int j0 = 0; j0 < HD; j0 += 32)
            s += (p.bc[j0 + lane] + p.bw[j0 + lane]) * p.linW[(size_t)(j0 + lane) * NOUT + wo];
        #pragma unroll
        for (int off = 16; off; off >>= 1)
            s += __shfl_xor_sync(0xffffffff, s, off);
        if (lane == 0) p.linb2[wo] = p.linb[wo] + s;
    } else {
        int task = (b - 559) * 8 + (threadIdx.x >> 5);
        if (task >= XS_TASKS) return;
        int lane = threadIdx.x & 31;
        int arr  = task / (MTILES * 128);
        int rem  = task - arr * (MTILES * 128);
        int tile = rem >> 7;
        int sub  = rem & 127;
        int c    = sub >> 5;
        int k8c  = (sub >> 3) & 3;
        int m16  = sub & 7;

        const float* x = p.xs[arr];
        int r_lo = m16 * 16 + (lane >> 2);
        int n0 = tile * 128 + r_lo;
        int n1 = n0 + 8;
        int kb = c * 32 + k8c * 8 + (lane & 3);
        float e0 = (n0 < NN) ? x[(size_t)n0 * HD + kb]     : 0.f;
        float e1 = (n1 < NN) ? x[(size_t)n1 * HD + kb]     : 0.f;
        float e2 = (n0 < NN) ? x[(size_t)n0 * HD + kb + 4] : 0.f;
        float e3 = (n1 < NN) ? x[(size_t)n1 * HD + kb + 4] : 0.f;
        uint4 o = make_uint4(f2tf32(e0), f2tf32(e1), f2tf32(e2), f2tf32(e3));
        uint32_t* dst = p.XSF[arr] + (size_t)tile * TW + c * 4096
                        + (k8c * 8 + m16) * 128 + lane * 4;
        *reinterpret_cast<uint4*>(dst) = o;
    }
}

// ---------------- dst-side projections ----------------
struct ProjP {
    const float* x[2];
    const float* V[2];
    float*       out[2];
};

__global__ void __launch_bounds__(256) proj_dst_kernel(ProjP p, int n)
{
    int s = blockIdx.y;
    const float* x = p.x[s];
    const float* V = p.V[s];
    float* out = p.out[s];

    int lane   = threadIdx.x & 31;
    int warp   = (blockIdx.x * blockDim.x + threadIdx.x) >> 5;
    int nwarps = (gridDim.x * blockDim.x) >> 5;

    const float4* V4 = reinterpret_cast<const float4*>(V);
    float4 v0 = V4[lane * 4 + 0];
    float4 v1 = V4[lane * 4 + 1];
    float4 v2 = V4[lane * 4 + 2];
    float4 v3 = V4[lane * 4 + 3];

    const float4* x4 = reinterpret_cast<const float4*>(x);
    for (int node = warp; node < n; node += nwarps) {
        float4 xv = x4[(size_t)node * 32 + lane];
        float4 a;
        a.x = xv.x * v0.x + xv.y * v1.x + xv.z * v2.x + xv.w * v3.x;
        a.y = xv.x * v0.y + xv.y * v1.y + xv.z * v2.y + xv.w * v3.y;
        a.z = xv.x * v0.z + xv.y * v1.z + xv.z * v2.z + xv.w * v3.z;
        a.w = xv.x * v0.w + xv.y * v1.w + xv.z * v2.w + xv.w * v3.w;
        #pragma unroll
        for (int off = 16; off; off >>= 1) {
            a.x += __shfl_xor_sync(0xffffffff, a.x, off);
            a.y += __shfl_xor_sync(0xffffffff, a.y, off);
            a.z += __shfl_xor_sync(0xffffffff, a.z, off);
            a.w += __shfl_xor_sync(0xffffffff, a.w, off);
        }
        if (lane == 0)
            reinterpret_cast<float4*>(out)[node] = a;
    }
}

// ---------------- CSR gather (batch-4 edges, fragment-layout output) -------
struct GJob {
    const int*   off[2];
    const int*   srcids[2];
    const float* h[2];
    const float* AS[2];
    const float* AD[2];
    const float* b1;
    const float* b2;
    const float* V;
    uint32_t*    XF;     // fragment-layout output
    float*       P;
    int nrel;
    int act;
};
struct GatherP { GJob job[2]; };

__global__ void __launch_bounds__(256) gather_kernel(GatherP gp)
{
    const GJob p = gp.job[blockIdx.y];
    int warp = (blockIdx.x * blockDim.x + threadIdx.x) >> 5;
    int lane = threadIdx.x & 31;
    if (warp >= NN) return;
    const int dst = warp;
    const int hh  = lane >> 3;

    float4 sum = make_float4(0.f, 0.f, 0.f, 0.f);
    if (p.b1) {
        sum = reinterpret_cast<const float4*>(p.b1)[lane];
        if (p.b2) {
            float4 t = reinterpret_cast<const float4*>(p.b2)[lane];
            sum.x += t.x; sum.y += t.y; sum.z += t.z; sum.w += t.w;
        }
    }

    for (int r = 0; r < p.nrel; r++) {
        int beg = p.off[r][dst];
        int end = p.off[r][dst + 1];
        if (beg == end) continue;
        float ad = p.AD[r][dst * HH + hh];
        const float* hbase = p.h[r];
        const float* as = p.AS[r];
        const int* sid = p.srcids[r];
        float4 a = make_float4(0.f, 0.f, 0.f, 0.f);
        float Z = 0.f;
        int e = beg;
        for (; e + 4 <= end; e += 4) {
            int sv = sid[e + (lane & 3)];
            int s0 = __shfl_sync(0xffffffff, sv, 0);
            int s1 = __shfl_sync(0xffffffff, sv, 1);
            int s2 = __shfl_sync(0xffffffff, sv, 2);
            int s3 = __shfl_sync(0xffffffff, sv, 3);
            float t0 = as[s0 * HH + hh] + ad;
            float t1 = as[s1 * HH + hh] + ad;
            float t2 = as[s2 * HH + hh] + ad;
            float t3 = as[s3 * HH + hh] + ad;
            float4 h0 = *reinterpret_cast<const float4*>(hbase + (size_t)s0 * HD + lane * 4);
            float4 h1 = *reinterpret_cast<const float4*>(hbase + (size_t)s1 * HD + lane * 4);
            float4 h2 = *reinterpret_cast<const float4*>(hbase + (size_t)s2 * HD + lane * 4);
            float4 h3 = *reinterpret_cast<const float4*>(hbase + (size_t)s3 * HD + lane * 4);
            t0 = fmaxf(t0, 0.2f * t0); t1 = fmaxf(t1, 0.2f * t1);
            t2 = fmaxf(t2, 0.2f * t2); t3 = fmaxf(t3, 0.2f * t3);
            float w0 = __expf(t0), w1 = __expf(t1);
            float w2 = __expf(t2), w3 = __expf(t3);
            a.x += w0 * h0.x + w1 * h1.x + w2 * h2.x + w3 * h3.x;
            a.y += w0 * h0.y + w1 * h1.y + w2 * h2.y + w3 * h3.y;
            a.z += w0 * h0.z + w1 * h1.z + w2 * h2.z + w3 * h3.z;
            a.w += w0 * h0.w + w1 * h1.w + w2 * h2.w + w3 * h3.w;
            Z += (w0 + w1) + (w2 + w3);
        }
        for (; e < end; e++) {
            int src = sid[e];
            float t = as[src * HH + hh] + ad;
            t = fmaxf(t, 0.2f * t);
            float w = __expf(t);
            float4 hv = *reinterpret_cast<const float4*>(hbase + (size_t)src * HD + lane * 4);
            a.x += w * hv.x; a.y += w * hv.y; a.z += w * hv.z; a.w += w * hv.w;
            Z += w;
        }
        float inv = 1.f / (Z + 1e-16f);
        sum.x += a.x * inv; sum.y += a.y * inv; sum.z += a.z * inv; sum.w += a.w * inv;
    }

    if (p.act) {
        sum.x = fmaxf(sum.x, 0.01f * sum.x);
        sum.y = fmaxf(sum.y, 0.01f * sum.y);
        sum.z = fmaxf(sum.z, 0.01f * sum.z);
        sum.w = fmaxf(sum.w, 0.01f * sum.w);
    }

    // fragment-layout store: element k = lane*4+q of row dst
    {
        int r = dst & 127;
        uint32_t* F = p.XF + (size_t)(dst >> 7) * TW;
        int chunkc = lane >> 3;
        int kc = lane & 7;
        int k8c = kc >> 1;
        int reg = ((kc & 1) << 1) | ((r >> 3) & 1);
        uint32_t* base = F + chunkc * 4096 + (k8c * 8 + (r >> 4)) * 128 + reg;
        int rb = (r & 7) * 4;
        base[(rb + 0) * 4] = f2tf32(sum.x);
        base[(rb + 1) * 4] = f2tf32(sum.y);
        base[(rb + 2) * 4] = f2tf32(sum.z);
        base[(rb + 3) * 4] = f2tf32(sum.w);
    }

    if (p.V) {
        const float4* V4 = reinterpret_cast<const float4*>(p.V);
        float4 v0 = V4[lane * 4 + 0];
        float4 v1 = V4[lane * 4 + 1];
        float4 v2 = V4[lane * 4 + 2];
        float4 v3 = V4[lane * 4 + 3];
        float4 a;
        a.x = sum.x * v0.x + sum.y * v1.x + sum.z * v2.x + sum.w * v3.x;
        a.y = sum.x * v0.y + sum.y * v1.y + sum.z * v2.y + sum.w * v3.y;
        a.z = sum.x * v0.z + sum.y * v1.z + sum.z * v2.z + sum.w * v3.z;
        a.w = sum.x * v0.w + sum.y * v1.w + sum.z * v2.w + sum.w * v3.w;
        #pragma unroll
        for (int off = 16; off; off >>= 1) {
            a.x += __shfl_xor_sync(0xffffffff, a.x, off);
            a.y += __shfl_xor_sync(0xffffffff, a.y, off);
            a.z += __shfl_xor_sync(0xffffffff, a.z, off);
            a.w += __shfl_xor_sync(0xffffffff, a.w, off);
        }
        if (lane == 0)
            reinterpret_cast<float4*>(p.P)[dst] = a;
    }
}

// ---------------- tf32 GEMM v7: BOTH operands pre-fragmented ---------------
// B (64KB) staged once at prologue; A chunks (16KB) double-buffered —
// all via contiguous cp.async, zero conversion work in the loop.
__device__ __forceinline__ void mma_tf32(float& c0, float& c1, float& c2, float& c3,
                                         uint32_t a0, uint32_t a1, uint32_t a2, uint32_t a3,
                                         uint32_t b0, uint32_t b1)
{
    asm volatile(
        "mma.sync.aligned.m16n8k8.row.col.f32.tf32.tf32.f32 "
        "{%0,%1,%2,%3}, {%4,%5,%6,%7}, {%8,%9}, {%0,%1,%2,%3};"
        : "+f"(c0), "+f"(c1), "+f"(c2), "+f"(c3)
        : "r"(a0), "r"(a1), "r"(a2), "r"(a3), "r"(b0), "r"(b1));
}

__device__ __forceinline__ void cp_async16(uint32_t dst, const void* src) {
    asm volatile("cp.async.cg.shared.global [%0], [%1], 16;"
                 :: "r"(dst), "l"(src));
}

struct GemmZ {
    const uint32_t* Afrag;
    const uint32_t* Bfrag;   // +blockIdx.y*TW per n-tile
    float*          C;
    const float*    attS;
    const float*    attD;
    float*          PS;
    float*          PD;
};
struct GemmP {
    GemmZ z[3];
    const float* bias;
    int M, Nc;
};

#define GEMM_SMEM_BYTES (65536 + 32768)   // Bf full-K + Af double buffer

template <bool CALIGNED>
__global__ void __launch_bounds__(256, 2) gemm_v7_kernel(GemmP p)
{
    extern __shared__ uint8_t smem_raw[];
    uint32_t* Bf = reinterpret_cast<uint32_t*>(smem_raw);   // 16384 words
    uint32_t* Af = Bf + 16384;                              // 2 x 4096 words

    const uint32_t sBf = (uint32_t)__cvta_generic_to_shared(Bf);
    const uint32_t sAf = (uint32_t)__cvta_generic_to_shared(Af);

    const GemmZ zp = p.z[blockIdx.z];
    const int M = p.M, Nc = p.Nc;

    const int tid  = threadIdx.x;
    const int lane = tid & 31;
    const int w    = tid >> 5;
    const int wm   = w & 1;
    const int wn   = w >> 1;
    const int m0   = blockIdx.x * 128;
    const int n0   = blockIdx.y * 128;

    const uint32_t* BFg = zp.Bfrag + (size_t)blockIdx.y * TW;
    const uint32_t* AFg = zp.Afrag + (size_t)blockIdx.x * TW;

    // prologue: full B fragments (group 0)
    #pragma unroll
    for (int it = 0; it < 16; it++) {
        int off = it * 256 + tid;                 // float4 index 0..4095
        cp_async16(sBf + off * 16, BFg + off * 4);
    }
    asm volatile("cp.async.commit_group;" ::: "memory");

    auto stageA = [&](int c, int buf) {
        #pragma unroll
        for (int it = 0; it < 4; it++) {
            int off = it * 256 + tid;             // float4 index 0..1023
            cp_async16(sAf + (buf * 1024 + off) * 16, AFg + c * 4096 + off * 4);
        }
        asm volatile("cp.async.commit_group;" ::: "memory");
    };

    stageA(0, 0);   // group 1
    stageA(1, 1);   // group 2

    float acc[4][4][4];
    #pragma unroll
    for (int i = 0; i < 4; i++)
        #pragma unroll
        for (int j = 0; j < 4; j++)
            #pragma unroll
            for (int q = 0; q < 4; q++) acc[i][j][q] = 0.f;

    #pragma unroll
    for (int c = 0; c < 4; c++) {
        if (c < 3) { asm volatile("cp.async.wait_group 1;" ::: "memory"); }
        else       { asm volatile("cp.async.wait_group 0;" ::: "memory"); }
        __syncthreads();

        uint32_t* AfB = Af + (c & 1) * 4096;
        #pragma unroll
        for (int k8c = 0; k8c < 4; k8c++) {
            uint32_t a[4][4];
            uint32_t b[4][2];
            #pragma unroll
            for (int i = 0; i < 4; i++) {
                uint4 t = *reinterpret_cast<uint4*>(&AfB[((k8c << 3) + wm * 4 + i) * 128 + (lane << 2)]);
                a[i][0] = t.x; a[i][1] = t.y; a[i][2] = t.z; a[i][3] = t.w;
            }
            #pragma unroll
            for (int j = 0; j < 4; j++) {
                uint2 t = *reinterpret_cast<uint2*>(
                    &Bf[(((c << 2) + k8c) * 16 + wn * 4 + j) * 64 + (lane << 1)]);
                b[j][0] = t.x; b[j][1] = t.y;
            }
            #pragma unroll
            for (int i = 0; i < 4; i++)
                #pragma unroll
                for (int j = 0; j < 4; j++)
                    mma_tf32(acc[i][j][0], acc[i][j][1], acc[i][j][2], acc[i][j][3],
                             a[i][0], a[i][1], a[i][2], a[i][3], b[j][0], b[j][1]);
        }

        if (c < 2) {
            __syncthreads();            // all warps done reading Af[c&1]
            stageA(c + 2, c & 1);
        }
    }

    // ---- epilogue: C write ----
    const int gID = lane >> 2;
    const int tig = lane & 3;
    const float* bias = p.bias;
    #pragma unroll
    for (int i = 0; i < 4; i++) {
        int row0 = m0 + wm * 64 + i * 16 + gID;
        #pragma unroll
        for (int j = 0; j < 4; j++) {
            int col = n0 + wn * 32 + j * 8 + tig * 2;
            float bx = 0.f, by = 0.f;
            if (bias) {
                if (col < Nc)     bx = bias[col];
                if (col + 1 < Nc) by = bias[col + 1];
            }
            if (CALIGNED) {
                if (row0 < M) {
                    float2 o = make_float2(acc[i][j][0] + bx, acc[i][j][1] + by);
                    *reinterpret_cast<float2*>(zp.C + (size_t)row0 * Nc + col) = o;
                }
                if (row0 + 8 < M) {
                    float2 o = make_float2(acc[i][j][2] + bx, acc[i][j][3] + by);
                    *reinterpret_cast<float2*>(zp.C + (size_t)(row0 + 8) * Nc + col) = o;
                }
            } else {
                if (row0 < M) {
                    if (col < Nc)     zp.C[(size_t)row0 * Nc + col]     = acc[i][j][0] + bx;
                    if (col + 1 < Nc) zp.C[(size_t)row0 * Nc + col + 1] = acc[i][j][1] + by;
                }
                if (row0 + 8 < M) {
                    if (col < Nc)     zp.C[(size_t)(row0 + 8) * Nc + col]     = acc[i][j][2] + bx;
                    if (col + 1 < Nc) zp.C[(size_t)(row0 + 8) * Nc + col + 1] = acc[i][j][3] + by;
                }
            }
        }
    }

    // ---- epilogue: attention dots (head == warp column wn) ----
    if (zp.attS) {
        bool hasD = (zp.attD != nullptr);
        float aS[4][2], aD[4][2];
        #pragma unroll
        for (int j = 0; j < 4; j++) {
            int cc = wn * 32 + j * 8 + tig * 2;
            aS[j][0] = zp.attS[cc];
            aS[j][1] = zp.attS[cc + 1];
            if (hasD) { aD[j][0] = zp.attD[cc]; aD[j][1] = zp.attD[cc + 1]; }
        }
        #pragma unroll
        for (int i = 0; i < 4; i++) {
            float s0 = 0.f, s1 = 0.f, d0 = 0.f, d1 = 0.f;
            #pragma unroll
            for (int j = 0; j < 4; j++) {
                s0 += acc[i][j][0] * aS[j][0] + acc[i][j][1] * aS[j][1];
                s1 += acc[i][j][2] * aS[j][0] + acc[i][j][3] * aS[j][1];
                if (hasD) {
                    d0 += acc[i][j][0] * aD[j][0] + acc[i][j][1] * aD[j][1];
                    d1 += acc[i][j][2] * aD[j][0] + acc[i][j][3] * aD[j][1];
                }
            }
            s0 += __shfl_xor_sync(0xffffffff, s0, 1); s0 += __shfl_xor_sync(0xffffffff, s0, 2);
            s1 += __shfl_xor_sync(0xffffffff, s1, 1); s1 += __shfl_xor_sync(0xffffffff, s1, 2);
            if (hasD) {
                d0 += __shfl_xor_sync(0xffffffff, d0, 1); d0 += __shfl_xor_sync(0xffffffff, d0, 2);
                d1 += __shfl_xor_sync(0xffffffff, d1, 1); d1 += __shfl_xor_sync(0xffffffff, d1, 2);
            }
            if (tig == 0) {
                int r0 = m0 + wm * 64 + i * 16 + gID;
                if (r0 < M)     zp.PS[(size_t)r0 * HH + wn]       = s0;
                if (r0 + 8 < M) zp.PS[(size_t)(r0 + 8) * HH + wn] = s1;
                if (hasD) {
                    if (r0 < M)     zp.PD[(size_t)r0 * HH + wn]       = d0;
                    if (r0 + 8 < M) zp.PD[(size_t)(r0 + 8) * HH + wn] = d1;
                }
            }
        }
    }
}

// ---------------- host launch ----------------
extern "C" void kernel_launch(void* const* d_in, const int* in_sizes, int n_in,
                              void* d_out, int out_size)
{
    const float* xs[2]   = {nullptr, nullptr}; int nx = 0;
    const int*   eis[3]  = {nullptr, nullptr, nullptr}; int ne = 0;
    const float* Ws[6]   = {}; int nw = 0;
    const float* attb[18]= {}; int na = 0;
    const float* linW = nullptr;
    const float* linb = nullptr;

    for (int i = 0; i < n_in; i++) {
        int s = in_sizes[i];
        if      (s == NN * HD    && nx < 2)  xs[nx++]   = (const float*)d_in[i];
        else if (s == 2 * EE     && ne < 3)  eis[ne++]  = (const int*)d_in[i];
        else if (s == HD * HD    && nw < 6)  Ws[nw++]   = (const float*)d_in[i];
        else if (s == HD         && na < 18) attb[na++] = (const float*)d_in[i];
        else if (s == HD * NOUT)             linW       = (const float*)d_in[i];
        else if (s == NOUT)                  linb       = (const float*)d_in[i];
    }
    if (nx != 2 || ne != 3 || nw != 6 || na != 18 || !linW || !linb) return;

    static bool attr_done = false;
    if (!attr_done) {
        cudaFuncSetAttribute(gemm_v7_kernel<true>,
                             cudaFuncAttributeMaxDynamicSharedMemorySize, GEMM_SMEM_BYTES);
        cudaFuncSetAttribute(gemm_v7_kernel<false>,
                             cudaFuncAttributeMaxDynamicSharedMemorySize, GEMM_SMEM_BYTES);
        attr_done = true;
    }

    float *pH, *pP, *pV, *pLB2;
    uint32_t *pWF, *pXSF, *pXF;
    int *pCNT, *pCUR, *pOFF, *pSRC;
    cudaGetSymbolAddress((void**)&pH,   g_H);
    cudaGetSymbolAddress((void**)&pP,   g_P);
    cudaGetSymbolAddress((void**)&pV,   g_V);
    cudaGetSymbolAddress((void**)&pLB2, g_LB2);
    cudaGetSymbolAddress((void**)&pWF,  g_WF);
    cudaGetSymbolAddress((void**)&pXSF, g_XSF);
    cudaGetSymbolAddress((void**)&pXF,  g_XF);
    cudaGetSymbolAddress((void**)&pCNT, g_CNT);
    cudaGetSymbolAddress((void**)&pCUR, g_CUR);
    cudaGetSymbolAddress((void**)&pOFF, g_OFF);
    cudaGetSymbolAddress((void**)&pSRC, g_SRC);

    const size_t FEAT = (size_t)NN * HD;
    const size_t FTW  = (size_t)MTILES * TW;
    float* H0  = pH;
    float* H1  = pH + FEAT;
    float* H2  = pH + 2 * FEAT;
    uint32_t* XSF0 = pXSF;
    uint32_t* XSF1 = pXSF + FTW;
    uint32_t* XPF1 = pXF;
    uint32_t* XAF1 = pXF + FTW;
    uint32_t* XPF2 = pXF + 2 * FTW;
    float* Pb[7];
    for (int i = 0; i < 7; i++) Pb[i] = pP + (size_t)i * NN * HH;
    float* v0 = pV;
    float* v1 = pV + 512;
    float* v2 = pV + 1024;
    const int* OFFr[3] = {pOFF, pOFF + (NN + 1), pOFF + 2 * (NN + 1)};
    const int* SRCr[3] = {pSRC, pSRC + EE, pSRC + 2 * EE};

    cudaMemsetAsync(pCNT, 0, 3 * NN * sizeof(int));

    // CSR build
    EdgeP ep;
    ep.ei[0] = eis[0]; ep.ei[1] = eis[1]; ep.ei[2] = eis[2];
    ep.cnt = pCNT; ep.cur = pCUR; ep.srcout = pSRC;
    hist_kernel<<<dim3((EE + 255) / 256, 3), 256>>>(ep);
    scan_kernel<<<3, 1024>>>(pCNT, pOFF, pCUR);
    fill_kernel<<<dim3((EE + 255) / 256, 3), 256>>>(ep);

    // prep: V vectors + B frags + folded bias + xs fragment images
    PrepParams pp;
    pp.Wv[0] = Ws[1]; pp.att[0] = attb[4];    // ad0_w
    pp.Wv[1] = Ws[2]; pp.att[1] = attb[7];    // ad0_wb
    pp.Wv[2] = Ws[4]; pp.att[2] = attb[13];   // ad1_w
    pp.V = pV;
    pp.Wm[0] = Ws[0]; pp.Wm[1] = Ws[1]; pp.Wm[2] = Ws[2];
    pp.Wm[3] = Ws[3]; pp.Wm[4] = Ws[4];
    pp.linW = linW; pp.WF = pWF;
    pp.linb = linb; pp.bc = attb[11]; pp.bw = attb[14]; pp.linb2 = pLB2;
    pp.xs[0] = xs[0]; pp.xs[1] = xs[1];
    pp.XSF[0] = XSF0; pp.XSF[1] = XSF1;
    prep_all_kernel<<<559 + XS_BLOCKS, 256>>>(pp);

    // L0 GEMMs + epilogue attention dots
    GemmP g0 = {};
    g0.z[0] = {XSF0, pWF + 0 * TW, H0, attb[0], attb[1], Pb[0], Pb[1]};
    g0.z[1] = {XSF1, pWF + 1 * TW, H1, attb[3], nullptr, Pb[2], nullptr};
    g0.z[2] = {XSF0, pWF + 2 * TW, H2, attb[6], nullptr, Pb[4], nullptr};
    g0.bias = nullptr; g0.M = NN; g0.Nc = HD;
    gemm_v7_kernel<true><<<dim3(MTILES, 1, 3), 256, GEMM_SMEM_BYTES>>>(g0);

    // dst-side projections for L0
    ProjP prj;
    prj.x[0] = xs[0]; prj.V[0] = v0; prj.out[0] = Pb[3];
    prj.x[1] = xs[1]; prj.V[1] = v1; prj.out[1] = Pb[5];
    proj_dst_kernel<<<dim3(512, 2), 256>>>(prj, NN);

    // L0 gather (frag-layout outputs)
    GatherP ga0 = {};
    ga0.job[0].off[0] = OFFr[0]; ga0.job[0].srcids[0] = SRCr[0];
    ga0.job[0].h[0] = H0; ga0.job[0].AS[0] = Pb[0]; ga0.job[0].AD[0] = Pb[1];
    ga0.job[0].off[1] = OFFr[1]; ga0.job[0].srcids[1] = SRCr[1];
    ga0.job[0].h[1] = H1; ga0.job[0].AS[1] = Pb[2]; ga0.job[0].AD[1] = Pb[3];
    ga0.job[0].b1 = attb[2]; ga0.job[0].b2 = attb[5];
    ga0.job[0].V = v2; ga0.job[0].XF = XPF1; ga0.job[0].P = Pb[6];
    ga0.job[0].nrel = 2; ga0.job[0].act = 1;
    ga0.job[1].off[0] = OFFr[2]; ga0.job[1].srcids[0] = SRCr[2];
    ga0.job[1].h[0] = H2; ga0.job[1].AS[0] = Pb[4]; ga0.job[1].AD[0] = Pb[5];
    ga0.job[1].b1 = attb[8]; ga0.job[1].b2 = nullptr;
    ga0.job[1].V = nullptr; ga0.job[1].XF = XAF1; ga0.job[1].P = nullptr;
    ga0.job[1].nrel = 1; ga0.job[1].act = 1;
    gather_kernel<<<dim3((NN * 32 + 255) / 256, 2), 256>>>(ga0);

    // L1 GEMMs + epilogue dots
    GemmP g1 = {};
    g1.z[0] = {XPF1, pWF + 3 * TW, H0, attb[9],  attb[10], Pb[0], Pb[1]};
    g1.z[1] = {XAF1, pWF + 4 * TW, H1, attb[12], nullptr,  Pb[2], nullptr};
    g1.z[2] = g1.z[0];
    g1.bias = nullptr; g1.M = NN; g1.Nc = HD;
    gemm_v7_kernel<true><<<dim3(MTILES, 1, 2), 256, GEMM_SMEM_BYTES>>>(g1);

    // L1 gather -> XPF2 (bias folded into classifier)
    GatherP ga1 = {};
    ga1.job[0].off[0] = OFFr[0]; ga1.job[0].srcids[0] = SRCr[0];
    ga1.job[0].h[0] = H0; ga1.job[0].AS[0] = Pb[0]; ga1.job[0].AD[0] = Pb[1];
    ga1.job[0].off[1] = OFFr[1]; ga1.job[0].srcids[1] = SRCr[1];
    ga1.job[0].h[1] = H1; ga1.job[0].AS[1] = Pb[2]; ga1.job[0].AD[1] = Pb[6];
    ga1.job[0].b1 = nullptr; ga1.job[0].b2 = nullptr;
    ga1.job[0].V = nullptr; ga1.job[0].XF = XPF2; ga1.job[0].P = nullptr;
    ga1.job[0].nrel = 2; ga1.job[0].act = 0;
    gather_kernel<<<dim3((NN * 32 + 255) / 256, 1), 256>>>(ga1);

    // classifier GEMM (bias folded)
    GemmP gc = {};
    gc.z[0] = {XPF2, pWF + 5 * TW, (float*)d_out, nullptr, nullptr, nullptr, nullptr};
    gc.z[1] = gc.z[0];
    gc.z[2] = gc.z[0];
    gc.bias = pLB2; gc.M = NN; gc.Nc = NOUT;
    gemm_v7_kernel<false><<<dim3(MTILES, 3, 1), 256, GEMM_SMEM_BYTES>>>(gc);
}

// round 12
// speedup vs baseline: 1.1063x; 1.1063x over previous
#include <cuda_runtime.h>
#include <cstdint>

// ---------------- problem constants ----------------
#define NN      100000
#define EE      250000
#define HH      4
#define HD      128
#define NOUT    349
#define TW      16384
#define SCB     98            // scan blocks per relation (98*1024 >= NN)

// ---------------- device scratch ----------------
__device__ float    g_H  [3ll * NN * HD];   // per-relation h = x@W
__device__ float    g_X  [3ll * NN * HD];   // XP1, XA1, XP2
__device__ float    g_P  [7ll * NN * HH];   // attention logit buffers [n*4+h]
__device__ float    g_V  [3 * HD * HH];     // W·att_d vectors
__device__ float    g_LB2[NOUT];            // folded classifier bias
__device__ uint32_t g_WF [8 * TW];          // pre-fragmented tf32 B matrices
__device__ int      g_CNT[3 * NN];
__device__ int      g_CUR[3 * NN];
__device__ int      g_OFF[3 * (NN + 1)];
__device__ int      g_SRC[3ll * EE];
__device__ int      g_BS [3 * SCB];         // scan block sums

__device__ __forceinline__ uint32_t f2tf32(float x) {
    uint32_t r; asm("cvt.rna.tf32.f32 %0, %1;" : "=r"(r) : "f"(x)); return r;
}

// ---------------- CSR build ----------------
struct EdgeP { const int* ei[3]; int* cnt; int* cur; int* srcout; };

__global__ void hist_kernel(EdgeP p)
{
    int rel = blockIdx.y;
    int e = blockIdx.x * blockDim.x + threadIdx.x;
    if (e >= EE) return;
    int dst = p.ei[rel][EE + e];
    atomicAdd(&p.cnt[rel * NN + dst], 1);
}

// phase A: per-block sums of 1024 counts
__global__ void scanA_kernel(const int* cnt, int* bsum)
{
    int rel  = blockIdx.y;
    int base = blockIdx.x * 1024;
    const int* c = cnt + (size_t)rel * NN;
    int s = 0;
    #pragma unroll
    for (int i = 0; i < 4; i++) {
        int idx = base + i * 256 + threadIdx.x;
        if (idx < NN) s += c[idx];
    }
    __shared__ int ws[8];
    #pragma unroll
    for (int o = 16; o; o >>= 1) s += __shfl_xor_sync(0xffffffff, s, o);
    if ((threadIdx.x & 31) == 0) ws[threadIdx.x >> 5] = s;
    __syncthreads();
    if (threadIdx.x < 8) {
        int v = ws[threadIdx.x];
        #pragma unroll
        for (int o = 4; o; o >>= 1) v += __shfl_xor_sync(0xff, v, o);
        if (threadIdx.x == 0) bsum[rel * SCB + blockIdx.x] = v;
    }
}

// phase B: exclusive scan of block sums (in place) + sentinel
__global__ void scanB_kernel(int* bsum, int* off)
{
    __shared__ int sm[SCB];
    for (int rel = 0; rel < 3; rel++) {
        int* b = bsum + rel * SCB;
        if (threadIdx.x < SCB) sm[threadIdx.x] = b[threadIdx.x];
        __syncthreads();
        if (threadIdx.x == 0) {
            int acc = 0;
            for (int i = 0; i < SCB; i++) { int t = sm[i]; sm[i] = acc; acc += t; }
        }
        __syncthreads();
        if (threadIdx.x < SCB) b[threadIdx.x] = sm[threadIdx.x];
        if (threadIdx.x == 0) off[(size_t)rel * (NN + 1) + NN] = EE;
        __syncthreads();
    }
}

// phase C: local scan + add block prefix, write off/cur
__global__ void scanC_kernel(const int* cnt, const int* bsum, int* off, int* cur)
{
    int rel  = blockIdx.y;
    int base = blockIdx.x * 1024;
    const int* c = cnt + (size_t)rel * NN;
    int pre = bsum[rel * SCB + blockIdx.x];

    int lane = threadIdx.x & 31, wid = threadIdx.x >> 5;
    int idx0 = base + threadIdx.x * 4;
    int vals[4];
    int s = 0;
    #pragma unroll
    for (int i = 0; i < 4; i++) {
        int id = idx0 + i;
        int t = (id < NN) ? c[id] : 0;
        vals[i] = s; s += t;
    }
    int inc = s;
    #pragma unroll
    for (int d = 1; d < 32; d <<= 1) {
        int t = __shfl_up_sync(0xffffffff, inc, d);
        if (lane >= d) inc += t;
    }
    int wex = inc - s;
    __shared__ int ws[8];
    if (lane == 31) ws[wid] = inc;
    __syncthreads();
    if (wid == 0 && lane < 8) {
        int orig = ws[lane];
        int wi = orig;
        #pragma unroll
        for (int d = 1; d < 8; d <<= 1) {
            int t = __shfl_up_sync(0xff, wi, d);
            if (lane >= d) wi += t;
        }
        ws[lane] = wi - orig;
    }
    __syncthreads();
    int tex = pre + ws[wid] + wex;
    int* o  = off + (size_t)rel * (NN + 1);
    int* cu = cur + (size_t)rel * NN;
    #pragma unroll
    for (int i = 0; i < 4; i++) {
        int id = idx0 + i;
        if (id < NN) { int e = tex + vals[i]; o[id] = e; cu[id] = e; }
    }
}

__global__ void fill_kernel(EdgeP p)
{
    int rel = blockIdx.y;
    int e = blockIdx.x * blockDim.x + threadIdx.x;
    if (e >= EE) return;
    int src = p.ei[rel][e];
    int dst = p.ei[rel][EE + e];
    int pos = atomicAdd(&p.cur[rel * NN + dst], 1);
    p.srcout[(size_t)rel * EE + pos] = src;
}

// ---------------- prep: V vectors + B frags + folded bias ------------------
struct PrepParams {
    const float* Wv[3];
    const float* att[3];
    float* V;
    const float* Wm[5];
    const float* linW;
    uint32_t* WF;
    const float* linb;
    const float* bc;
    const float* bw;
    float* linb2;
};

__global__ void prep_all_kernel(PrepParams p)
{
    int b = blockIdx.x;
    if (b < 3) {
        int k = threadIdx.x;
        if (k >= HD) return;
        const float* W   = p.Wv[b];
        const float* att = p.att[b];
        #pragma unroll
        for (int h = 0; h < HH; h++) {
            float s = 0.f;
            #pragma unroll
            for (int c = 0; c < 32; c++)
                s += W[k * HD + h * 32 + c] * att[h * 32 + c];
            p.V[b * (HD * HH) + k * HH + h] = s;
        }
    } else if (b < 515) {
        int t = (b - 3) * 256 + threadIdx.x;
        int m   = t >> 14;
        int idx = t & 16383;
        int n   = idx & 127;
        int kr  = idx >> 7;
        float val;
        if (m < 5) {
            val = p.Wm[m][kr * HD + n];
        } else {
            int col = (m - 5) * 128 + n;
            val = (col < NOUT) ? p.linW[(size_t)kr * NOUT + col] : 0.f;
        }
        int c = kr >> 5, krl = kr & 31;
        uint32_t word = (uint32_t)(((krl >> 3) * 16 + (n >> 3)) * 64
                                   + ((n & 7) * 4 + (krl & 3)) * 2
                                   + ((krl >> 2) & 1));
        p.WF[m * TW + c * 4096 + word] = f2tf32(val);
    } else {
        int wo   = (b - 515) * 8 + (threadIdx.x >> 5);
        int lane = threadIdx.x & 31;
        if (wo >= NOUT) return;
        float s = 0.f;
        #pragma unroll
        for (int j0 = 0; j0 < HD; j0 += 32)
            s += (p.bc[j0 + lane] + p.bw[j0 + lane]) * p.linW[(size_t)(j0 + lane) * NOUT + wo];
        #pragma unroll
        for (int off = 16; off; off >>= 1)
            s += __shfl_xor_sync(0xffffffff, s, off);
        if (lane == 0) p.linb2[wo] = p.linb[wo] + s;
    }
}

// ---------------- dst-side projections ----------------
struct ProjP {
    const float* x[2];
    const float* V[2];
    float*       out[2];
};

__global__ void __launch_bounds__(256) proj_dst_kernel(ProjP p, int n)
{
    int s = blockIdx.y;
    const float* x = p.x[s];
    const float* V = p.V[s];
    float* out = p.out[s];

    int lane   = threadIdx.x & 31;
    int warp   = (blockIdx.x * blockDim.x + threadIdx.x) >> 5;
    int nwarps = (gridDim.x * blockDim.x) >> 5;

    const float4* V4 = reinterpret_cast<const float4*>(V);
    float4 v0 = V4[lane * 4 + 0];
    float4 v1 = V4[lane * 4 + 1];
    float4 v2 = V4[lane * 4 + 2];
    float4 v3 = V4[lane * 4 + 3];

    const float4* x4 = reinterpret_cast<const float4*>(x);
    for (int node = warp; node < n; node += nwarps) {
        float4 xv = x4[(size_t)node * 32 + lane];
        float4 a;
        a.x = xv.x * v0.x + xv.y * v1.x + xv.z * v2.x + xv.w * v3.x;
        a.y = xv.x * v0.y + xv.y * v1.y + xv.z * v2.y + xv.w * v3.y;
        a.z = xv.x * v0.z + xv.y * v1.z + xv.z * v2.z + xv.w * v3.z;
        a.w = xv.x * v0.w + xv.y * v1.w + xv.z * v2.w + xv.w * v3.w;
        #pragma unroll
        for (int off = 16; off; off >>= 1) {
            a.x += __shfl_xor_sync(0xffffffff, a.x, off);
            a.y += __shfl_xor_sync(0xffffffff, a.y, off);
            a.z += __shfl_xor_sync(0xffffffff, a.z, off);
            a.w += __shfl_xor_sync(0xffffffff, a.w, off);
        }
        if (lane == 0)
            reinterpret_cast<float4*>(out)[node] = a;
    }
}

// ---------------- CSR gather (batch-4 edges, row-major output) -------------
struct GJob {
    const int*   off[2];
    const int*   srcids[2];
    const float* h[2];
    const float* AS[2];
    const float* AD[2];
    const float* b1;
    const float* b2;
    const float* V;
    float*       X;
    float*       P;
    int nrel;
    int act;
};
struct GatherP { GJob job[2]; };

__global__ void __launch_bounds__(256) gather_kernel(GatherP gp)
{
    const GJob p = gp.job[blockIdx.y];
    int warp = (blockIdx.x * blockDim.x + threadIdx.x) >> 5;
    int lane = threadIdx.x & 31;
    if (warp >= NN) return;
    const int dst = warp;
    const int hh  = lane >> 3;

    float4 sum = make_float4(0.f, 0.f, 0.f, 0.f);
    if (p.b1) {
        sum = reinterpret_cast<const float4*>(p.b1)[lane];
        if (p.b2) {
            float4 t = reinterpret_cast<const float4*>(p.b2)[lane];
            sum.x += t.x; sum.y += t.y; sum.z += t.z; sum.w += t.w;
        }
    }

    for (int r = 0; r < p.nrel; r++) {
        int beg = p.off[r][dst];
        int end = p.off[r][dst + 1];
        if (beg == end) continue;
        float ad = p.AD[r][dst * HH + hh];
        const float* hbase = p.h[r];
        const float* as = p.AS[r];
        const int* sid = p.srcids[r];
        float4 a = make_float4(0.f, 0.f, 0.f, 0.f);
        float Z = 0.f;
        int e = beg;
        for (; e + 4 <= end; e += 4) {
            int sv = sid[e + (lane & 3)];
            int s0 = __shfl_sync(0xffffffff, sv, 0);
            int s1 = __shfl_sync(0xffffffff, sv, 1);
            int s2 = __shfl_sync(0xffffffff, sv, 2);
            int s3 = __shfl_sync(0xffffffff, sv, 3);
            float t0 = as[s0 * HH + hh] + ad;
            float t1 = as[s1 * HH + hh] + ad;
            float t2 = as[s2 * HH + hh] + ad;
            float t3 = as[s3 * HH + hh] + ad;
            float4 h0 = *reinterpret_cast<const float4*>(hbase + (size_t)s0 * HD + lane * 4);
            float4 h1 = *reinterpret_cast<const float4*>(hbase + (size_t)s1 * HD + lane * 4);
            float4 h2 = *reinterpret_cast<const float4*>(hbase + (size_t)s2 * HD + lane * 4);
            float4 h3 = *reinterpret_cast<const float4*>(hbase + (size_t)s3 * HD + lane * 4);
            t0 = fmaxf(t0, 0.2f * t0); t1 = fmaxf(t1, 0.2f * t1);
            t2 = fmaxf(t2, 0.2f * t2); t3 = fmaxf(t3, 0.2f * t3);
            float w0 = __expf(t0), w1 = __expf(t1);
            float w2 = __expf(t2), w3 = __expf(t3);
            a.x += w0 * h0.x + w1 * h1.x + w2 * h2.x + w3 * h3.x;
            a.y += w0 * h0.y + w1 * h1.y + w2 * h2.y + w3 * h3.y;
            a.z += w0 * h0.z + w1 * h1.z + w2 * h2.z + w3 * h3.z;
            a.w += w0 * h0.w + w1 * h1.w + w2 * h2.w + w3 * h3.w;
            Z += (w0 + w1) + (w2 + w3);
        }
        for (; e < end; e++) {
            int src = sid[e];
            float t = as[src * HH + hh] + ad;
            t = fmaxf(t, 0.2f * t);
            float w = __expf(t);
            float4 hv = *reinterpret_cast<const float4*>(hbase + (size_t)src * HD + lane * 4);
            a.x += w * hv.x; a.y += w * hv.y; a.z += w * hv.z; a.w += w * hv.w;
            Z += w;
        }
        float inv = 1.f / (Z + 1e-16f);
        sum.x += a.x * inv; sum.y += a.y * inv; sum.z += a.z * inv; sum.w += a.w * inv;
    }

    if (p.act) {
        sum.x = fmaxf(sum.x, 0.01f * sum.x);
        sum.y = fmaxf(sum.y, 0.01f * sum.y);
        sum.z = fmaxf(sum.z, 0.01f * sum.z);
        sum.w = fmaxf(sum.w, 0.01f * sum.w);
    }
    reinterpret_cast<float4*>(p.X)[(size_t)dst * 32 + lane] = sum;

    if (p.V) {
        const float4* V4 = reinterpret_cast<const float4*>(p.V);
        float4 v0 = V4[lane * 4 + 0];
        float4 v1 = V4[lane * 4 + 1];
        float4 v2 = V4[lane * 4 + 2];
        float4 v3 = V4[lane * 4 + 3];
        float4 a;
        a.x = sum.x * v0.x + sum.y * v1.x + sum.z * v2.x + sum.w * v3.x;
        a.y = sum.x * v0.y + sum.y * v1.y + sum.z * v2.y + sum.w * v3.y;
        a.z = sum.x * v0.z + sum.y * v1.z + sum.z * v2.z + sum.w * v3.z;
        a.w = sum.x * v0.w + sum.y * v1.w + sum.z * v2.w + sum.w * v3.w;
        #pragma unroll
        for (int off = 16; off; off >>= 1) {
            a.x += __shfl_xor_sync(0xffffffff, a.x, off);
            a.y += __shfl_xor_sync(0xffffffff, a.y, off);
            a.z += __shfl_xor_sync(0xffffffff, a.z, off);
            a.w += __shfl_xor_sync(0xffffffff, a.w, off);
        }
        if (lane == 0)
            reinterpret_cast<float4*>(p.P)[dst] = a;
    }
}

// ---------------- tf32 GEMM v6: pre-fragmented B, resident full-K ----------
__device__ __forceinline__ void mma_tf32(float& c0, float& c1, float& c2, float& c3,
                                         uint32_t a0, uint32_t a1, uint32_t a2, uint32_t a3,
                                         uint32_t b0, uint32_t b1)
{
    asm volatile(
        "mma.sync.aligned.m16n8k8.row.col.f32.tf32.tf32.f32 "
        "{%0,%1,%2,%3}, {%4,%5,%6,%7}, {%8,%9}, {%0,%1,%2,%3};"
        : "+f"(c0), "+f"(c1), "+f"(c2), "+f"(c3)
        : "r"(a0), "r"(a1), "r"(a2), "r"(a3), "r"(b0), "r"(b1));
}

__device__ __forceinline__ void cp_async16(uint32_t dst, const void* src, int sz) {
    asm volatile("cp.async.cg.shared.global [%0], [%1], 16, %2;"
                 :: "r"(dst), "l"(src), "r"(sz));
}

struct GemmZ {
    const float*    A;
    const uint32_t* Bfrag;
    float*          C;
    const float*    attS;
    const float*    attD;
    float*          PS;
    float*          PD;
};
struct GemmP {
    GemmZ z[3];
    const float* bias;
    int M, Nc;
};

#define GEMM_SMEM_BYTES (65536 + 16384 + 32768)

template <bool CALIGNED>
__global__ void __launch_bounds__(256, 2) gemm_v6_kernel(GemmP p)
{
    extern __shared__ uint8_t smem_raw[];
    uint32_t* Bf   = reinterpret_cast<uint32_t*>(smem_raw);
    uint32_t* Af   = Bf + 16384;
    float4*   rawA = reinterpret_cast<float4*>(Af + 4096);

    const uint32_t sBf = (uint32_t)__cvta_generic_to_shared(Bf);
    const uint32_t sA  = (uint32_t)__cvta_generic_to_shared(rawA);

    const GemmZ zp = p.z[blockIdx.z];
    const int M = p.M, Nc = p.Nc;

    const int tid  = threadIdx.x;
    const int lane = tid & 31;
    const int w    = tid >> 5;
    const int wm   = w & 1;
    const int wn   = w >> 1;
    const int m0   = blockIdx.x * 128;
    const int n0   = blockIdx.y * 128;

    const int gA   = lane >> 3;
    const int kcA  = lane & 7;
    const int rotA = (gA + (kcA >> 1)) & 3;

    const uint32_t* BFg = zp.Bfrag + (size_t)blockIdx.y * TW;

    #pragma unroll
    for (int it = 0; it < 16; it++) {
        int off = it * 256 + tid;
        cp_async16(sBf + off * 16, BFg + off * 4, 16);
    }
    asm volatile("cp.async.commit_group;" ::: "memory");

    auto stageA = [&](int c, int buf) {
        #pragma unroll
        for (int it = 0; it < 4; it++) {
            int qg = it * 8 + w;
            int r  = qg * 4 + gA;
            int gm = m0 + r;
            uint32_t dst = sA + (buf * 1024 + qg * 32 + lane) * 16;
            const float* src = zp.A + (size_t)gm * 128 + c * 32 + kcA * 4;
            cp_async16(dst, src, (gm < M) ? 16 : 0);
        }
        asm volatile("cp.async.commit_group;" ::: "memory");
    };

    auto convertA = [&](int buf) {
        int k8c = kcA >> 1;
        int khi = kcA & 1;
        #pragma unroll
        for (int it = 0; it < 4; it++) {
            int qg = it * 8 + w;
            int r  = qg * 4 + gA;
            float4 v = rawA[buf * 1024 + qg * 32 + lane];
            int reg = (khi << 1) | ((r >> 3) & 1);
            uint32_t* base = &Af[((k8c << 3) + (r >> 4)) * 128 + reg];
            float vals[4] = {v.x, v.y, v.z, v.w};
            #pragma unroll
            for (int s = 0; s < 4; s++) {
                int j = (s + rotA) & 3;
                base[(((r & 7) << 2) + j) << 2] = f2tf32(vals[j]);
            }
        }
    };

    stageA(0, 0);
    stageA(1, 1);

    float acc[4][4][4];
    #pragma unroll
    for (int i = 0; i < 4; i++)
        #pragma unroll
        for (int j = 0; j < 4; j++)
            #pragma unroll
            for (int q = 0; q < 4; q++) acc[i][j][q] = 0.f;

    #pragma unroll
    for (int c = 0; c < 4; c++) {
        if (c < 3) { asm volatile("cp.async.wait_group 1;" ::: "memory"); }
        else       { asm volatile("cp.async.wait_group 0;" ::: "memory"); }
        __syncthreads();
        convertA(c & 1);
        __syncthreads();
        if (c + 2 < 4) stageA(c + 2, c & 1);

        #pragma unroll
        for (int k8c = 0; k8c < 4; k8c++) {
            uint32_t a[4][4];
            uint32_t b[4][2];
            #pragma unroll
            for (int i = 0; i < 4; i++) {
                uint4 t = *reinterpret_cast<uint4*>(&Af[((k8c << 3) + wm * 4 + i) * 128 + (lane << 2)]);
                a[i][0] = t.x; a[i][1] = t.y; a[i][2] = t.z; a[i][3] = t.w;
            }
            #pragma unroll
            for (int j = 0; j < 4; j++) {
                uint2 t = *reinterpret_cast<uint2*>(
                    &Bf[(((c << 2) + k8c) * 16 + wn * 4 + j) * 64 + (lane << 1)]);
                b[j][0] = t.x; b[j][1] = t.y;
            }
            #pragma unroll
            for (int i = 0; i < 4; i++)
                #pragma unroll
                for (int j = 0; j < 4; j++)
                    mma_tf32(acc[i][j][0], acc[i][j][1], acc[i][j][2], acc[i][j][3],
                             a[i][0], a[i][1], a[i][2], a[i][3], b[j][0], b[j][1]);
        }
    }

    const int gID = lane >> 2;
    const int tig = lane & 3;
    const float* bias = p.bias;
    #pragma unroll
    for (int i = 0; i < 4; i++) {
        int row0 = m0 + wm * 64 + i * 16 + gID;
        #pragma unroll
        for (int j = 0; j < 4; j++) {
            int col = n0 + wn * 32 + j * 8 + tig * 2;
            float bx = 0.f, by = 0.f;
            if (bias) {
                if (col < Nc)     bx = bias[col];
                if (col + 1 < Nc) by = bias[col + 1];
            }
            if (CALIGNED) {
                if (row0 < M) {
                    float2 o = make_float2(acc[i][j][0] + bx, acc[i][j][1] + by);
                    *reinterpret_cast<float2*>(zp.C + (size_t)row0 * Nc + col) = o;
                }
                if (row0 + 8 < M) {
                    float2 o = make_float2(acc[i][j][2] + bx, acc[i][j][3] + by);
                    *reinterpret_cast<float2*>(zp.C + (size_t)(row0 + 8) * Nc + col) = o;
                }
            } else {
                if (row0 < M) {
                    if (col < Nc)     zp.C[(size_t)row0 * Nc + col]     = acc[i][j][0] + bx;
                    if (col + 1 < Nc) zp.C[(size_t)row0 * Nc + col + 1] = acc[i][j][1] + by;
                }
                if (row0 + 8 < M) {
                    if (col < Nc)     zp.C[(size_t)(row0 + 8) * Nc + col]     = acc[i][j][2] + bx;
                    if (col + 1 < Nc) zp.C[(size_t)(row0 + 8) * Nc + col + 1] = acc[i][j][3] + by;
                }
            }
        }
    }

    if (zp.attS) {
        bool hasD = (zp.attD != nullptr);
        float aS[4][2], aD[4][2];
        #pragma unroll
        for (int j = 0; j < 4; j++) {
            int cc = wn * 32 + j * 8 + tig * 2;
            aS[j][0] = zp.attS[cc];
            aS[j][1] = zp.attS[cc + 1];
            if (hasD) { aD[j][0] = zp.attD[cc]; aD[j][1] = zp.attD[cc + 1]; }
        }
        #pragma unroll
        for (int i = 0; i < 4; i++) {
            float s0 = 0.f, s1 = 0.f, d0 = 0.f, d1 = 0.f;
            #pragma unroll
            for (int j = 0; j < 4; j++) {
                s0 += acc[i][j][0] * aS[j][0] + acc[i][j][1] * aS[j][1];
                s1 += acc[i][j][2] * aS[j][0] + acc[i][j][3] * aS[j][1];
                if (hasD) {
                    d0 += acc[i][j][0] * aD[j][0] + acc[i][j][1] * aD[j][1];
                    d1 += acc[i][j][2] * aD[j][0] + acc[i][j][3] * aD[j][1];
                }
            }
            s0 += __shfl_xor_sync(0xffffffff, s0, 1); s0 += __shfl_xor_sync(0xffffffff, s0, 2);
            s1 += __shfl_xor_sync(0xffffffff, s1, 1); s1 += __shfl_xor_sync(0xffffffff, s1, 2);
            if (hasD) {
                d0 += __shfl_xor_sync(0xffffffff, d0, 1); d0 += __shfl_xor_sync(0xffffffff, d0, 2);
                d1 += __shfl_xor_sync(0xffffffff, d1, 1); d1 += __shfl_xor_sync(0xffffffff, d1, 2);
            }
            if (tig == 0) {
                int r0 = m0 + wm * 64 + i * 16 + gID;
                if (r0 < M)     zp.PS[(size_t)r0 * HH + wn]       = s0;
                if (r0 + 8 < M) zp.PS[(size_t)(r0 + 8) * HH + wn] = s1;
                if (hasD) {
                    if (r0 < M)     zp.PD[(size_t)r0 * HH + wn]       = d0;
                    if (r0 + 8 < M) zp.PD[(size_t)(r0 + 8) * HH + wn] = d1;
                }
            }
        }
    }
}

// ---------------- host launch ----------------
extern "C" void kernel_launch(void* const* d_in, const int* in_sizes, int n_in,
                              void* d_out, int out_size)
{
    const float* xs[2]   = {nullptr, nullptr}; int nx = 0;
    const int*   eis[3]  = {nullptr, nullptr, nullptr}; int ne = 0;
    const float* Ws[6]   = {}; int nw = 0;
    const float* attb[18]= {}; int na = 0;
    const float* linW = nullptr;
    const float* linb = nullptr;

    for (int i = 0; i < n_in; i++) {
        int s = in_sizes[i];
        if      (s == NN * HD    && nx < 2)  xs[nx++]   = (const float*)d_in[i];
        else if (s == 2 * EE     && ne < 3)  eis[ne++]  = (const int*)d_in[i];
        else if (s == HD * HD    && nw < 6)  Ws[nw++]   = (const float*)d_in[i];
        else if (s == HD         && na < 18) attb[na++] = (const float*)d_in[i];
        else if (s == HD * NOUT)             linW       = (const float*)d_in[i];
        else if (s == NOUT)                  linb       = (const float*)d_in[i];
    }
    if (nx != 2 || ne != 3 || nw != 6 || na != 18 || !linW || !linb) return;

    static bool attr_done = false;
    if (!attr_done) {
        cudaFuncSetAttribute(gemm_v6_kernel<true>,
                             cudaFuncAttributeMaxDynamicSharedMemorySize, GEMM_SMEM_BYTES);
        cudaFuncSetAttribute(gemm_v6_kernel<false>,
                             cudaFuncAttributeMaxDynamicSharedMemorySize, GEMM_SMEM_BYTES);
        attr_done = true;
    }

    float *pH, *pX, *pP, *pV, *pLB2;
    uint32_t* pWF;
    int *pCNT, *pCUR, *pOFF, *pSRC, *pBS;
    cudaGetSymbolAddress((void**)&pH,   g_H);
    cudaGetSymbolAddress((void**)&pX,   g_X);
    cudaGetSymbolAddress((void**)&pP,   g_P);
    cudaGetSymbolAddress((void**)&pV,   g_V);
    cudaGetSymbolAddress((void**)&pLB2, g_LB2);
    cudaGetSymbolAddress((void**)&pWF,  g_WF);
    cudaGetSymbolAddress((void**)&pCNT, g_CNT);
    cudaGetSymbolAddress((void**)&pCUR, g_CUR);
    cudaGetSymbolAddress((void**)&pOFF, g_OFF);
    cudaGetSymbolAddress((void**)&pSRC, g_SRC);
    cudaGetSymbolAddress((void**)&pBS,  g_BS);

    const size_t FEAT = (size_t)NN * HD;
    float* H0  = pH;
    float* H1  = pH + FEAT;
    float* H2  = pH + 2 * FEAT;
    float* XP1 = pX;
    float* XA1 = pX + FEAT;
    float* XP2 = pX + 2 * FEAT;
    float* Pb[7];
    for (int i = 0; i < 7; i++) Pb[i] = pP + (size_t)i * NN * HH;
    float* v0 = pV;
    float* v1 = pV + 512;
    float* v2 = pV + 1024;
    const int* OFFr[3] = {pOFF, pOFF + (NN + 1), pOFF + 2 * (NN + 1)};
    const int* SRCr[3] = {pSRC, pSRC + EE, pSRC + 2 * EE};

    cudaMemsetAsync(pCNT, 0, 3 * NN * sizeof(int));

    // CSR build (parallel 3-phase scan)
    EdgeP ep;
    ep.ei[0] = eis[0]; ep.ei[1] = eis[1]; ep.ei[2] = eis[2];
    ep.cnt = pCNT; ep.cur = pCUR; ep.srcout = pSRC;
    hist_kernel<<<dim3((EE + 255) / 256, 3), 256>>>(ep);
    scanA_kernel<<<dim3(SCB, 3), 256>>>(pCNT, pBS);
    scanB_kernel<<<1, 128>>>(pBS, pOFF);
    scanC_kernel<<<dim3(SCB, 3), 256>>>(pCNT, pBS, pOFF, pCUR);
    fill_kernel<<<dim3((EE + 255) / 256, 3), 256>>>(ep);

    // prep: V vectors + B frags + folded bias
    PrepParams pp;
    pp.Wv[0] = Ws[1]; pp.att[0] = attb[4];    // ad0_w
    pp.Wv[1] = Ws[2]; pp.att[1] = attb[7];    // ad0_wb
    pp.Wv[2] = Ws[4]; pp.att[2] = attb[13];   // ad1_w
    pp.V = pV;
    pp.Wm[0] = Ws[0]; pp.Wm[1] = Ws[1]; pp.Wm[2] = Ws[2];
    pp.Wm[3] = Ws[3]; pp.Wm[4] = Ws[4];
    pp.linW = linW; pp.WF = pWF;
    pp.linb = linb; pp.bc = attb[11]; pp.bw = attb[14]; pp.linb2 = pLB2;
    prep_all_kernel<<<515 + (NOUT + 7) / 8, 256>>>(pp);

    // L0 GEMMs + epilogue attention dots
    GemmP g0 = {};
    g0.z[0] = {xs[0], pWF + 0 * TW, H0, attb[0], attb[1], Pb[0], Pb[1]};
    g0.z[1] = {xs[1], pWF + 1 * TW, H1, attb[3], nullptr, Pb[2], nullptr};
    g0.z[2] = {xs[0], pWF + 2 * TW, H2, attb[6], nullptr, Pb[4], nullptr};
    g0.bias = nullptr; g0.M = NN; g0.Nc = HD;
    gemm_v6_kernel<true><<<dim3((NN + 127) / 128, 1, 3), 256, GEMM_SMEM_BYTES>>>(g0);

    // dst-side projections for L0
    ProjP prj;
    prj.x[0] = xs[0]; prj.V[0] = v0; prj.out[0] = Pb[3];
    prj.x[1] = xs[1]; prj.V[1] = v1; prj.out[1] = Pb[5];
    proj_dst_kernel<<<dim3(512, 2), 256>>>(prj, NN);

    // L0 gather
    GatherP ga0 = {};
    ga0.job[0].off[0] = OFFr[0]; ga0.job[0].srcids[0] = SRCr[0];
    ga0.job[0].h[0] = H0; ga0.job[0].AS[0] = Pb[0]; ga0.job[0].AD[0] = Pb[1];
    ga0.job[0].off[1] = OFFr[1]; ga0.job[0].srcids[1] = SRCr[1];
    ga0.job[0].h[1] = H1; ga0.job[0].AS[1] = Pb[2]; ga0.job[0].AD[1] = Pb[3];
    ga0.job[0].b1 = attb[2]; ga0.job[0].b2 = attb[5];
    ga0.job[0].V = v2; ga0.job[0].X = XP1; ga0.job[0].P = Pb[6];
    ga0.job[0].nrel = 2; ga0.job[0].act = 1;
    ga0.job[1].off[0] = OFFr[2]; ga0.job[1].srcids[0] = SRCr[2];
    ga0.job[1].h[0] = H2; ga0.job[1].AS[0] = Pb[4]; ga0.job[1].AD[0] = Pb[5];
    ga0.job[1].b1 = attb[8]; ga0.job[1].b2 = nullptr;
    ga0.job[1].V = nullptr; ga0.job[1].X = XA1; ga0.job[1].P = nullptr;
    ga0.job[1].nrel = 1; ga0.job[1].act = 1;
    gather_kernel<<<dim3((NN * 32 + 255) / 256, 2), 256>>>(ga0);

    // L1 GEMMs + epilogue dots
    GemmP g1 = {};
    g1.z[0] = {XP1, pWF + 3 * TW, H0, attb[9],  attb[10], Pb[0], Pb[1]};
    g1.z[1] = {XA1, pWF + 4 * TW, H1, attb[12], nullptr,  Pb[2], nullptr};
    g1.z[2] = g1.z[0];
    g1.bias = nullptr; g1.M = NN; g1.Nc = HD;
    gemm_v6_kernel<true><<<dim3((NN + 127) / 128, 1, 2), 256, GEMM_SMEM_BYTES>>>(g1);

    // L1 gather -> XP2 (bias folded into classifier)
    GatherP ga1 = {};
    ga1.job[0].off[0] = OFFr[0]; ga1.job[0].srcids[0] = SRCr[0];
    ga1.job[0].h[0] = H0; ga1.job[0].AS[0] = Pb[0]; ga1.job[0].AD[0] = Pb[1];
    ga1.job[0].off[1] = OFFr[1]; ga1.job[0].srcids[1] = SRCr[1];
    ga1.job[0].h[1] = H1; ga1.job[0].AS[1] = Pb[2]; ga1.job[0].AD[1] = Pb[6];
    ga1.job[0].b1 = nullptr; ga1.job[0].b2 = nullptr;
    ga1.job[0].V = nullptr; ga1.job[0].X = XP2; ga1.job[0].P = nullptr;
    ga1.job[0].nrel = 2; ga1.job[0].act = 0;
    gather_kernel<<<dim3((NN * 32 + 255) / 256, 1), 256>>>(ga1);

    // classifier GEMM (pre-fragmented padded linW tiles; bias folded)
    GemmP gc = {};
    gc.z[0] = {XP2, pWF + 5 * TW, (float*)d_out, nullptr, nullptr, nullptr, nullptr};
    gc.z[1] = gc.z[0];
    gc.z[2] = gc.z[0];
    gc.bias = pLB2; gc.M = NN; gc.Nc = NOUT;
    gemm_v6_kernel<false><<<dim3((NN + 127) / 128, 3, 1), 256, GEMM_SMEM_BYTES>>>(gc);
}